// round 2
// baseline (speedup 1.0000x reference)
#include <cuda_runtime.h>

// out[:, :DIM]  = p + a * tanh(q)
// out[:, DIM:]  = q
// where p = pq[:, :DIM], q = pq[:, DIM:], DIM = 2048, rows = 16384.
//
// Strategy: one thread handles one float4 of p AND the matching float4 of q,
// so every input byte is read exactly once and every output byte written once.
// Pure HBM-streaming kernel; float4 transactions.

template <int HALF4>  // float4s per half-row (DIM/4)
__global__ __launch_bounds__(256)
void fused_tanh_kernel(const float4* __restrict__ pq,
                       const float4* __restrict__ a,
                       float4* __restrict__ out,
                       int n_pairs) {
    int i = blockIdx.x * blockDim.x + threadIdx.x;
    if (i >= n_pairs) return;

    int row = i / HALF4;          // HALF4 is a power-of-two compile-time const
    int c   = i - row * HALF4;
    long base = (long)row * (2 * HALF4);

    float4 p  = pq[base + c];
    float4 q  = pq[base + HALF4 + c];
    float4 av = __ldg(&a[c]);

    float4 r;
    r.x = fmaf(av.x, tanhf(q.x), p.x);
    r.y = fmaf(av.y, tanhf(q.y), p.y);
    r.z = fmaf(av.z, tanhf(q.z), p.z);
    r.w = fmaf(av.w, tanhf(q.w), p.w);

    out[base + c]         = r;
    out[base + HALF4 + c] = q;
}

// Generic fallback (runtime HALF4) in case shapes ever differ.
__global__ __launch_bounds__(256)
void fused_tanh_kernel_generic(const float4* __restrict__ pq,
                               const float4* __restrict__ a,
                               float4* __restrict__ out,
                               int n_pairs, int half4) {
    int i = blockIdx.x * blockDim.x + threadIdx.x;
    if (i >= n_pairs) return;

    int row = i / half4;
    int c   = i - row * half4;
    long base = (long)row * (2 * half4);

    float4 p  = pq[base + c];
    float4 q  = pq[base + half4 + c];
    float4 av = __ldg(&a[c]);

    float4 r;
    r.x = fmaf(av.x, tanhf(q.x), p.x);
    r.y = fmaf(av.y, tanhf(q.y), p.y);
    r.z = fmaf(av.z, tanhf(q.z), p.z);
    r.w = fmaf(av.w, tanhf(q.w), p.w);

    out[base + c]         = r;
    out[base + half4 + c] = q;
}

extern "C" void kernel_launch(void* const* d_in, const int* in_sizes, int n_in,
                              void* d_out, int out_size) {
    const float4* pq = (const float4*)d_in[0];
    const float4* a  = (const float4*)d_in[1];
    float4*       out = (float4*)d_out;

    int dim    = in_sizes[1];              // 2048
    int total  = in_sizes[0];              // rows * 2*dim
    int rows   = total / (2 * dim);        // 16384
    int half4  = dim / 4;                  // 512
    int n_pairs = rows * half4;            // 8,388,608

    int threads = 256;
    int blocks  = (n_pairs + threads - 1) / threads;

    if (half4 == 512) {
        fused_tanh_kernel<512><<<blocks, threads>>>(pq, a, out, n_pairs);
    } else {
        fused_tanh_kernel_generic<<<blocks, threads>>>(pq, a, out, n_pairs, half4);
    }
}